// round 12
// baseline (speedup 1.0000x reference)
#include <cuda_runtime.h>
#include <cuda_fp16.h>
#include <cuda_bf16.h>
#include <cstdint>

// Problem constants (fixed shapes from reference)
#define BATCH      16
#define TLEN       1024
#define CCH        32
#define TC         (TLEN * CCH)        // 32768
#define KDIM       128
#define S_MAIN     128
#define NB_PATCH   400
#define P_TOP      60
#define P_OUT      (NB_PATCH + P_TOP)  // 460
#define STRETCH    8

#define THREADS    512                 // 16 warps; each warp owns up to 2 tasks
#define TPB        32                  // tasks (p columns) per block
#define SB         17                  // s_res row stride (conflict-free)
#define MAIN_PB    ((NB_PATCH + TPB - 1) / TPB)  // 13 (last width 16)
#define TOP_PB     ((P_TOP + TPB - 1) / TPB)     // 2  (last width 28)
#define MAIN_BLOCKS (S_MAIN * MAIN_PB) // 1664
#define TOP_BLOCKS  (TLEN * TOP_PB)    // 2048
#define ALL_BLOCKS  (MAIN_BLOCKS + TOP_BLOCKS)   // 3712

// Scratch: transposed fp16 x, xTh[tc][b]. One gather index pulls 16 halves
// = 32B (one L2 sector) holding all 16 batch values.
__device__ __align__(32) __half g_xTh[TC * BATCH];

// --------------------------------------------------------------------------
// Kernel 1: transpose + fp16-quantize x [B, T*C] -> xTh [T*C, B]
// --------------------------------------------------------------------------
__global__ void transpose_x_kernel(const float* __restrict__ x) {
    int tc = blockIdx.x * blockDim.x + threadIdx.x;
    if (tc >= TC) return;
    __half2 h[8];
#pragma unroll
    for (int b = 0; b < 8; b++) {
        h[b] = __floats2half2_rn(x[(2 * b) * TC + tc], x[(2 * b + 1) * TC + tc]);
    }
    uint4* dst = reinterpret_cast<uint4*>(g_xTh + tc * BATCH);
    unsigned int* hu = reinterpret_cast<unsigned int*>(h);
    dst[0] = make_uint4(hu[0], hu[1], hu[2], hu[3]);
    dst[1] = make_uint4(hu[4], hu[5], hu[6], hu[7]);
}

__device__ __forceinline__ float lrelu03(float v) {
    return (v > 0.f) ? v : 0.3f * v;
}

// --------------------------------------------------------------------------
// Kernel 2: fused main + top patch layers.
// Block = 16 warps covering 32 consecutive p of one (s|t) row.
// Warp w owns tasks pA = w and pB = w+16 (B skipped warp-uniformly if absent).
// Gather geometry: 8 lanes x 4B per row -> each LDG.32 touches only 4 distinct
// 128B lines (halves within-LDG replays vs the 8-line LDG.64 scheme).
// Lane roles: q=lane>>2, t=lane&3 (idx/W ownership);  g=lane>>3, c=lane&7
// (gather group / 4B slice = batches 2c,2c+1).
// idx/W are loaded as int4/float4 (128B per warp-load), own component t
// selected, then broadcast to gather groups with one SHFL.IDX (src=4r+g).
// Reduce across the 4 groups via shfl_xor(8,16); store via padded smem,
// warp = batch, 32 lanes = 32 consecutive p (128B STG rows).
// --------------------------------------------------------------------------
__global__ __launch_bounds__(THREADS, 2) void patchy_kernel(
    const float* __restrict__ W_main, const float* __restrict__ b_main,
    const float* __restrict__ W_top,  const float* __restrict__ b_top,
    const int*   __restrict__ idx_main, const int* __restrict__ idx_top,
    float* __restrict__ out)
{
    __shared__ float s_res[TPB * SB];

    const int tid  = threadIdx.x;
    const int w    = tid >> 5;       // warp id: local pA (compute) / batch (store)
    const int lane = tid & 31;
    const int q    = lane >> 2;      // idx/W ownership: which int4 slot
    const int t    = lane & 3;       // idx/W ownership: which component
    const int g    = lane >> 3;      // gather group (4 groups of 8 lanes)
    const int c    = lane & 7;       // 4B slice within 32B row = batches 2c,2c+1
    const bool is_main = (blockIdx.x < MAIN_BLOCKS);

    int st, p0, width;
    const int*   gi;
    const float* gw;
    const float* gb;
    if (is_main) {
        st    = blockIdx.x / MAIN_PB;
        p0    = (blockIdx.x - st * MAIN_PB) * TPB;
        width = min(TPB, NB_PATCH - p0);
        const long base = ((long)st * NB_PATCH + p0) * KDIM;
        gi = idx_main + base;
        gw = W_main   + base;
        gb = b_main   + st * NB_PATCH + p0;
    } else {
        const int b2 = blockIdx.x - MAIN_BLOCKS;
        st    = b2 >> 1;
        p0    = (b2 & 1) * TPB;
        width = min(TPB, P_TOP - p0);
        const long base = ((long)st * P_TOP + p0) * KDIM;
        gi = idx_top + base;
        gw = W_top   + base;
        gb = b_top   + st * P_TOP + p0;
    }

    const int  pA   = w;
    const int  pB   = w + 16;
    const bool hasB = (pB < width);   // warp-uniform

    const unsigned int* __restrict__ xT32 =
        reinterpret_cast<const unsigned int*>(g_xTh);

    const int4*   ipA = reinterpret_cast<const int4*>(gi + pA * KDIM);
    const float4* wpA = reinterpret_cast<const float4*>(gw + pA * KDIM);
    const int4*   ipB = reinterpret_cast<const int4*>(gi + pB * KDIM);
    const float4* wpB = reinterpret_cast<const float4*>(gw + pB * KDIM);

    float2 accA = make_float2(0.f, 0.f);
    float2 accB = make_float2(0.f, 0.f);

#pragma unroll
    for (int m = 0; m < 4; m++) {
        // ---- own idx/W (position m*32 + q*4 + t) ----
        const int4   IA = ipA[m * 8 + q];
        const float4 WA = wpA[m * 8 + q];
        const int   iA = (t == 0) ? IA.x : (t == 1) ? IA.y : (t == 2) ? IA.z : IA.w;
        const float fA = (t == 0) ? WA.x : (t == 1) ? WA.y : (t == 2) ? WA.z : WA.w;

        int   iB = 0; float fB = 0.f;
        if (hasB) {
            const int4   IB = ipB[m * 8 + q];
            const float4 WB = wpB[m * 8 + q];
            iB = (t == 0) ? IB.x : (t == 1) ? IB.y : (t == 2) ? IB.z : IB.w;
            fB = (t == 0) ? WB.x : (t == 1) ? WB.y : (t == 2) ? WB.z : WB.w;
        }

        // ---- broadcast + gather: instruction r serves 4 indices (1/group),
        //      4 distinct lines per LDG.32 ----
        unsigned int gA[8]; float wA[8];
#pragma unroll
        for (int r = 0; r < 8; r++) {
            const int src = 4 * r + g;
            const int ia  = __shfl_sync(0xffffffffu, iA, src);
            wA[r]         = __shfl_sync(0xffffffffu, fA, src);
            gA[r] = xT32[ia * 8 + c];
        }
        unsigned int gB[8]; float wB[8];
        if (hasB) {
#pragma unroll
            for (int r = 0; r < 8; r++) {
                const int src = 4 * r + g;
                const int ib  = __shfl_sync(0xffffffffu, iB, src);
                wB[r]         = __shfl_sync(0xffffffffu, fB, src);
                gB[r] = xT32[ib * 8 + c];
            }
        }

        // ---- FMAs (consume while next m's loads get scheduled) ----
#pragma unroll
        for (int r = 0; r < 8; r++) {
            const float2 v = __half22float2(*reinterpret_cast<const __half2*>(&gA[r]));
            accA.x = fmaf(v.x, wA[r], accA.x);
            accA.y = fmaf(v.y, wA[r], accA.y);
        }
        if (hasB) {
#pragma unroll
            for (int r = 0; r < 8; r++) {
                const float2 v = __half22float2(*reinterpret_cast<const __half2*>(&gB[r]));
                accB.x = fmaf(v.x, wB[r], accB.x);
                accB.y = fmaf(v.y, wB[r], accB.y);
            }
        }
    }

    // ---- reduce across the 4 gather groups (lanes c, c+8, c+16, c+24) ----
#pragma unroll
    for (int mask = 8; mask <= 16; mask <<= 1) {
        accA.x += __shfl_xor_sync(0xffffffffu, accA.x, mask);
        accA.y += __shfl_xor_sync(0xffffffffu, accA.y, mask);
        accB.x += __shfl_xor_sync(0xffffffffu, accB.x, mask);
        accB.y += __shfl_xor_sync(0xffffffffu, accB.y, mask);
    }

    // lanes 0..7 (g==0) hold batches (2c, 2c+1) fully reduced
    if (lane < 8) {
        {
            const float bias = gb[pA];
            s_res[pA * SB + 2 * c]     = lrelu03(accA.x + bias);
            s_res[pA * SB + 2 * c + 1] = lrelu03(accA.y + bias);
        }
        if (hasB) {
            const float bias = gb[pB];
            s_res[pB * SB + 2 * c]     = lrelu03(accB.x + bias);
            s_res[pB * SB + 2 * c + 1] = lrelu03(accB.y + bias);
        }
    }
    __syncthreads();

    // ---- Coalesced store: warp = batch, 32 lanes = 32 consecutive p ----
    if (lane < width) {
        const float y = s_res[lane * SB + w];   // stride-17 -> conflict-free
        if (is_main) {
            long o = (long)w * TLEN * P_OUT
                   + (long)(st * STRETCH) * P_OUT + p0 + lane;
#pragma unroll
            for (int r = 0; r < STRETCH; r++) {
                out[o + (long)r * P_OUT] = y;   // 128B rows per STG
            }
        } else {
            out[(long)w * TLEN * P_OUT + (long)st * P_OUT
                + NB_PATCH + p0 + lane] = y;
        }
    }
}

// --------------------------------------------------------------------------
// Inputs (metadata order): x, W_main, b_main, W_top, b_top, idx_main, idx_top
// --------------------------------------------------------------------------
extern "C" void kernel_launch(void* const* d_in, const int* in_sizes, int n_in,
                              void* d_out, int out_size) {
    const float* x        = (const float*)d_in[0];
    const float* W_main   = (const float*)d_in[1];
    const float* b_main   = (const float*)d_in[2];
    const float* W_top    = (const float*)d_in[3];
    const float* b_top    = (const float*)d_in[4];
    const int*   idx_main = (const int*)  d_in[5];
    const int*   idx_top  = (const int*)  d_in[6];
    float* out = (float*)d_out;

    transpose_x_kernel<<<(TC + 255) / 256, 256>>>(x);

    patchy_kernel<<<ALL_BLOCKS, THREADS>>>(W_main, b_main, W_top, b_top,
                                           idx_main, idx_top, out);
}